// round 16
// baseline (speedup 1.0000x reference)
#include <cuda_runtime.h>
#include <cuda_bf16.h>
#include <math.h>
#include <stdint.h>

typedef unsigned int u32; typedef unsigned long long u64;
#define BB 4
#define SS 512
#define DD 512
#define HH 8
#define DHH 64
#define FFD 2048
#define LL 6
#define VV 32000
#define MM (BB*SS)
#define QKVLD (3*DD)
#define CKVLD (2*DD)

__device__ float g_x[MM*DD], g_h[MM*DD], g_a[MM*DD], g_qkv[MM*3*DD];
__device__ float g_ckv[LL*MM*CKVLD];
__device__ float g_pr[MM*DD], g_dp[MM];
#define NW_SA (LL*4*DD*DD)
#define NW_F1 (LL*FFD*DD)
#define NW_OUT (VV*DD)
__device__ __nv_bfloat16 g_wsa_h[NW_SA], g_wsa_l[NW_SA], g_wca_h[NW_SA], g_wca_l[NW_SA];
__device__ __nv_bfloat16 g_wf1_h[NW_F1], g_wf1_l[NW_F1], g_wf2_h[NW_F1], g_wf2_l[NW_F1];
__device__ __nv_bfloat16 g_wo_h[NW_OUT], g_wo_l[NW_OUT], g_en_h[MM*DD], g_en_l[MM*DD];
__device__ __nv_bfloat16 g_xh[MM*DD], g_xl[MM*DD], g_hh[MM*DD], g_hl2[MM*DD];
__device__ __nv_bfloat16 g_ah[MM*DD], g_al[MM*DD], g_aoh[MM*DD], g_aol[MM*DD];
__device__ __nv_bfloat16 g_ffh[MM*FFD], g_ffl[MM*FFD];

__device__ __forceinline__ u32 smem_u32(const void* p) {
    u32 a; asm("{ .reg .u64 t; cvta.to.shared.u64 t, %1; cvt.u32.u64 %0, t; }" : "=r"(a) : "l"(p)); return a;
}
__device__ __forceinline__ void ldsm4(u32& r0, u32& r1, u32& r2, u32& r3, u32 addr) {
    asm volatile("ldmatrix.sync.aligned.m8n8.x4.shared.b16 {%0,%1,%2,%3}, [%4];"
                 : "=r"(r0), "=r"(r1), "=r"(r2), "=r"(r3) : "r"(addr));
}
__device__ __forceinline__ void mma16816(float* d, const u32* a, const u32* b) {
    asm volatile("mma.sync.aligned.m16n8k16.row.col.f32.bf16.bf16.f32 "
                 "{%0,%1,%2,%3}, {%4,%5,%6,%7}, {%8,%9}, {%0,%1,%2,%3};"
                 : "+f"(d[0]), "+f"(d[1]), "+f"(d[2]), "+f"(d[3])
                 : "r"(a[0]), "r"(a[1]), "r"(a[2]), "r"(a[3]), "r"(b[0]), "r"(b[1]));
}
__device__ __forceinline__ void cpa16(u32 saddr, const void* gaddr) {
    asm volatile("cp.async.cg.shared.global [%0], [%1], 16;" :: "r"(saddr), "l"(gaddr));
}
__device__ __forceinline__ void cpa_commit() { asm volatile("cp.async.commit_group;"); }
__device__ __forceinline__ void cpa_wait1()  { asm volatile("cp.async.wait_group 1;"); }
__device__ __forceinline__ void split_hl(float v, __nv_bfloat16& h, __nv_bfloat16& l) {
    h = __float2bfloat16(v); l = __float2bfloat16(v - __bfloat162float(h));
}

__global__ void cvt_hl(const float* __restrict__ s, __nv_bfloat16* __restrict__ hi,
                       __nv_bfloat16* __restrict__ lo, int n4) {
    int base = (blockIdx.x*blockDim.x + threadIdx.x)*4;
    #pragma unroll
    for (int j = 0; j < 4; j++) {
        int i = base + j;
        if (i >= n4) return;
        float4 v = ((const float4*)s)[i];
        __nv_bfloat16 h, l;
        split_hl(v.x,h,l); hi[i*4+0]=h; lo[i*4+0]=l;
        split_hl(v.y,h,l); hi[i*4+1]=h; lo[i*4+1]=l;
        split_hl(v.z,h,l); hi[i*4+2]=h; lo[i*4+2]=l;
        split_hl(v.w,h,l); hi[i*4+3]=h; lo[i*4+3]=l;
    }
}

// ==== HMMA split-3 GEMM, resident hi/lo tiles per stage, 3-stage cp.async ===
#define BK 64
#define SPITCH 72
#define TG_STAGES 3
#define WTILEE (128*SPITCH)
template<int RELU, int OUTHL, int MT, int RESID>
__global__ void __launch_bounds__(256)
tgemm(const __nv_bfloat16* __restrict__ Ah, const __nv_bfloat16* __restrict__ Al,
      const __nv_bfloat16* __restrict__ Wh, const __nv_bfloat16* __restrict__ Wl,
      const float* __restrict__ bias, float* __restrict__ C,
      __nv_bfloat16* __restrict__ Ch, __nv_bfloat16* __restrict__ Cl,
      const float* __restrict__ Res, int K, int ldc,
      size_t wstep, size_t bstep, size_t cstep)
{
    constexpr int ATILEE = MT*SPITCH;
    constexpr int STAGEE = 2*ATILEE + 2*WTILEE;
    constexpr int WM = MT/32;
    extern __shared__ __align__(16) __nv_bfloat16 sm[];
    const int zb = blockIdx.z;
    Wh += (size_t)zb*wstep; Wl += (size_t)zb*wstep;
    bias += (size_t)zb*bstep;
    if (!OUTHL) C += (size_t)zb*cstep;
    const int t = threadIdx.x, lane = t & 31, wid = t >> 5;
    const int m0 = blockIdx.y*MT, n0 = blockIdx.x*128;
    const int wm = wid >> 2, wn = wid & 3;
    const int mbase = wm*(MT/2), nbase = wn*32;
    const int mat = lane >> 3, rowin = lane & 7;
    const int a_row = (mat & 1)*8 + rowin, a_col = (mat >> 1)*8;
    const int b_row = (mat >> 1)*8 + rowin, b_col = (mat & 1)*8;
    const int wlrow = t >> 1, wlcol = (t & 1)*32;
    const int alrow = (MT == 128) ? (t >> 1) : (t >> 2);
    const int alcol = (MT == 128) ? ((t & 1)*32) : ((t & 3)*16);
    const int kc = K/BK;
    const u32 sbase = smem_u32(&sm[0]);

    float acc[WM][4][4];
    #pragma unroll
    for (int i = 0; i < WM; i++)
        #pragma unroll
        for (int j = 0; j < 4; j++)
            #pragma unroll
            for (int q = 0; q < 4; q++) acc[i][j][q] = 0.f;

    auto issue = [&](int c) {
        const int s = c % TG_STAGES;
        const int kq = c*BK;
        const __nv_bfloat16* ah = Ah + (size_t)(m0+alrow)*K + kq + alcol;
        const __nv_bfloat16* al = Al + (size_t)(m0+alrow)*K + kq + alcol;
        const __nv_bfloat16* wh = Wh + (size_t)(n0+wlrow)*K + kq + wlcol;
        const __nv_bfloat16* wl = Wl + (size_t)(n0+wlrow)*K + kq + wlcol;
        const u32 dah = sbase + (u32)((s*STAGEE + alrow*SPITCH + alcol)*2);
        const u32 dal = dah + (u32)(ATILEE*2);
        const u32 dwh = sbase + (u32)((s*STAGEE + 2*ATILEE + wlrow*SPITCH + wlcol)*2);
        const u32 dwl = dwh + (u32)(WTILEE*2);
        if (MT == 128) {
            cpa16(dah, ah); cpa16(dah+16, ah+8); cpa16(dah+32, ah+16); cpa16(dah+48, ah+24);
            cpa16(dal, al); cpa16(dal+16, al+8); cpa16(dal+32, al+16); cpa16(dal+48, al+24);
        } else {
            cpa16(dah, ah); cpa16(dah+16, ah+8);
            cpa16(dal, al); cpa16(dal+16, al+8);
        }
        cpa16(dwh, wh); cpa16(dwh+16, wh+8); cpa16(dwh+32, wh+16); cpa16(dwh+48, wh+24);
        cpa16(dwl, wl); cpa16(dwl+16, wl+8); cpa16(dwl+32, wl+16); cpa16(dwl+48, wl+24);
    };

    #pragma unroll
    for (int c = 0; c < TG_STAGES-1; c++) { issue(c); cpa_commit(); }

    for (int c = 0; c < kc; ++c) {
        cpa_wait1();
        __syncthreads();
        const int s = c % TG_STAGES;
        const u32 ahb = sbase + (u32)(s*STAGEE*2);
        const u32 alb = ahb + (u32)(ATILEE*2);
        const u32 whb = ahb + (u32)(2*ATILEE*2);
        const u32 wlb = whb + (u32)(WTILEE*2);
        #pragma unroll
        for (int seg = 0; seg < 3; seg++) {
            const u32 ab = (seg == 2) ? alb : ahb;
            const u32 wb = (seg == 1) ? wlb : whb;
            #pragma unroll
            for (int ks = 0; ks < BK/16; ks++) {
                u32 af[WM][4], bfr[2][4];
                #pragma unroll
                for (int mi = 0; mi < WM; mi++) {
                    u32 ad = ab + (u32)(((mbase + mi*16 + a_row)*SPITCH + ks*16 + a_col)*2);
                    ldsm4(af[mi][0], af[mi][1], af[mi][2], af[mi][3], ad);
                }
                #pragma unroll
                for (int g = 0; g < 2; g++) {
                    u32 bd = wb + (u32)(((nbase + g*16 + b_row)*SPITCH + ks*16 + b_col)*2);
                    ldsm4(bfr[g][0], bfr[g][1], bfr[g][2], bfr[g][3], bd);
                }
                #pragma unroll
                for (int mi = 0; mi < WM; mi++)
                    #pragma unroll
                    for (int ni = 0; ni < 4; ni++)
                        mma16816(acc[mi][ni], af[mi], &bfr[ni >> 1][(ni & 1)*2]);
            }
        }
        const int cn = c + TG_STAGES - 1;
        if (cn < kc) issue(cn);
        cpa_commit();
    }

    const int r = lane >> 2, c2 = (lane & 3) << 1;
    #pragma unroll
    for (int mi = 0; mi < WM; mi++) {
        #pragma unroll
        for (int ni = 0; ni < 4; ni++) {
            const int m = m0 + mbase + mi*16 + r;
            const int n = n0 + nbase + ni*8 + c2;
            float b0 = bias[n], b1 = bias[n+1];
            float v0 = acc[mi][ni][0] + b0, v1 = acc[mi][ni][1] + b1;
            float v2 = acc[mi][ni][2] + b0, v3 = acc[mi][ni][3] + b1;
            if (RESID) {
                float2 r0 = *(const float2*)(Res + (size_t)m*ldc + n);
                float2 r1 = *(const float2*)(Res + (size_t)(m+8)*ldc + n);
                v0 += r0.x; v1 += r0.y; v2 += r1.x; v3 += r1.y;
            }
            if (RELU) { v0=fmaxf(v0,0.f); v1=fmaxf(v1,0.f); v2=fmaxf(v2,0.f); v3=fmaxf(v3,0.f); }
            if (OUTHL) {
                __nv_bfloat16 h, l;
                size_t i0 = (size_t)m*ldc + n, i1 = (size_t)(m+8)*ldc + n;
                split_hl(v0,h,l); Ch[i0]=h;   Cl[i0]=l;
                split_hl(v1,h,l); Ch[i0+1]=h; Cl[i0+1]=l;
                split_hl(v2,h,l); Ch[i1]=h;   Cl[i1]=l;
                split_hl(v3,h,l); Ch[i1+1]=h; Cl[i1+1]=l;
            } else {
                *(float2*)(C + (size_t)m*ldc + n)     = make_float2(v0, v1);
                *(float2*)(C + (size_t)(m+8)*ldc + n) = make_float2(v2, v3);
            }
        }
    }
}
#define DSM(MT) (TG_STAGES*2*((MT)+128)*SPITCH*2)

// ======== fused flash attention =============================================
#define FA_SPQ 72
#define FA_SPP 136
#define FA_QE (128*FA_SPQ)
#define FA_PE (128*FA_SPP)
#define FA_VE (64*FA_SPP)
#define FA_DSMEM ((4*FA_QE + 2*FA_PE + 2*FA_VE)*2)
template<int CAUSAL>
__global__ void __launch_bounds__(256)
attn_fused(const float* __restrict__ Qp, int qld,
           const float* __restrict__ Kp, int kld,
           const float* __restrict__ Vp, int vld,
           const float* __restrict__ mask,
           __nv_bfloat16* __restrict__ oh, __nv_bfloat16* __restrict__ ol)
{
    extern __shared__ __align__(16) __nv_bfloat16 sm[];
    __nv_bfloat16 *Qh = sm,          *Ql = Qh + FA_QE;
    __nv_bfloat16 *Kh = Ql + FA_QE,  *Kl = Kh + FA_QE;
    __nv_bfloat16 *Ph = Kl + FA_QE,  *Pl = Ph + FA_PE;
    __nv_bfloat16 *Vh = Pl + FA_PE,  *Vl = Vh + FA_VE;
    __shared__ float rowm[128], rowl[128], rsc[128];
    __shared__ float spm[128][4], ssum[128][4];
    const int z = blockIdx.z, b = z >> 3, h = z & 7;
    const int q0 = blockIdx.y*128;
    const int t = threadIdx.x, lane = t & 31, wid = t >> 5;
    const int wm = wid >> 2, wn = wid & 3;
    const int mbase = wm*64, nbs = wn*32, nbo = wn*16;
    const int mat = lane >> 3, rowin = lane & 7;
    const int a_row = (mat & 1)*8 + rowin, a_col = (mat >> 1)*8;
    const int b_row = (mat >> 1)*8 + rowin, b_col = (mat & 1)*8;
    const int r = lane >> 2, c2 = (lane & 3) << 1;

    #pragma unroll
    for (int i = 0; i < 8; i++) {
        int fi = t + i*256, row = fi >> 4, col = (fi & 15)*4;
        float4 qv = *(const float4*)(Qp + (size_t)(b*SS + q0 + row)*qld + h*DHH + col);
        __nv_bfloat16 hh, ll; int o = row*FA_SPQ + col;
        split_hl(qv.x,hh,ll); Qh[o+0]=hh; Ql[o+0]=ll;
        split_hl(qv.y,hh,ll); Qh[o+1]=hh; Ql[o+1]=ll;
        split_hl(qv.z,hh,ll); Qh[o+2]=hh; Ql[o+2]=ll;
        split_hl(qv.w,hh,ll); Qh[o+3]=hh; Ql[o+3]=ll;
    }
    if (t < 128) { rowm[t] = -1e30f; rowl[t] = 0.f; }
    float acco[4][2][4];
    #pragma unroll
    for (int i = 0; i < 4; i++)
        #pragma unroll
        for (int j = 0; j < 2; j++)
            #pragma unroll
            for (int q = 0; q < 4; q++) acco[i][j][q] = 0.f;
    __syncthreads();

    for (int kt = 0; kt < 4; kt++) {
        const int k0 = kt*128;
        #pragma unroll
        for (int i = 0; i < 8; i++) {
            int fi = t + i*256, row = fi >> 4, col = (fi & 15)*4;
            float4 kv = *(const float4*)(Kp + (size_t)(b*SS + k0 + row)*kld + h*DHH + col);
            __nv_bfloat16 hh, ll; int o = row*FA_SPQ + col;
            split_hl(kv.x,hh,ll); Kh[o+0]=hh; Kl[o+0]=ll;
            split_hl(kv.y,hh,ll); Kh[o+1]=hh; Kl[o+1]=ll;
            split_hl(kv.z,hh,ll); Kh[o+2]=hh; Kl[o+2]=ll;
            split_hl(kv.w,hh,ll); Kh[o+3]=hh; Kl[o+3]=ll;
        }
        __syncthreads();
        float accs[4][4][4];
        #pragma unroll
        for (int i = 0; i < 4; i++)
            #pragma unroll
            for (int j = 0; j < 4; j++)
                #pragma unroll
                for (int q = 0; q < 4; q++) accs[i][j][q] = 0.f;
        #pragma unroll
        for (int seg = 0; seg < 3; seg++) {
            const u32 ab = smem_u32((seg == 2) ? Ql : Qh);
            const u32 wb = smem_u32((seg == 1) ? Kl : Kh);
            #pragma unroll
            for (int ks = 0; ks < 4; ks++) {
                u32 af[4][4], bfr[2][4];
                #pragma unroll
                for (int mi = 0; mi < 4; mi++) {
                    u32 ad = ab + (u32)(((mbase + mi*16 + a_row)*FA_SPQ + ks*16 + a_col)*2);
                    ldsm4(af[mi][0], af[mi][1], af[mi][2], af[mi][3], ad);
                }
                #pragma unroll
                for (int g = 0; g < 2; g++) {
                    u32 bd = wb + (u32)(((nbs + g*16 + b_row)*FA_SPQ + ks*16 + b_col)*2);
                    ldsm4(bfr[g][0], bfr[g][1], bfr[g][2], bfr[g][3], bd);
                }
                #pragma unroll
                for (int mi = 0; mi < 4; mi++)
                    #pragma unroll
                    for (int ni = 0; ni < 4; ni++)
                        mma16816(accs[mi][ni], af[mi], &bfr[ni >> 1][(ni & 1)*2]);
            }
        }
        float rmax[4][2];
        #pragma unroll
        for (int mi = 0; mi < 4; mi++) { rmax[mi][0] = -1e30f; rmax[mi][1] = -1e30f; }
        #pragma unroll
        for (int mi = 0; mi < 4; mi++)
            #pragma unroll
            for (int ni = 0; ni < 4; ni++)
                #pragma unroll
                for (int half = 0; half < 2; half++) {
                    const int m = q0 + mbase + mi*16 + r + half*8;
                    const int n = k0 + nbs + ni*8 + c2;
                    float mv0 = mask[b*SS + n], mv1 = mask[b*SS + n + 1];
                    if (CAUSAL && n   > m) mv0 = 1.0f;
                    if (CAUSAL && n+1 > m) mv1 = 1.0f;
                    float v0 = accs[mi][ni][half*2+0]*0.125f - mv0*1e6f;
                    float v1 = accs[mi][ni][half*2+1]*0.125f - mv1*1e6f;
                    accs[mi][ni][half*2+0] = v0; accs[mi][ni][half*2+1] = v1;
                    rmax[mi][half] = fmaxf(rmax[mi][half], fmaxf(v0, v1));
                }
        #pragma unroll
        for (int mi = 0; mi < 4; mi++)
            #pragma unroll
            for (int half = 0; half < 2; half++) {
                float mv = rmax[mi][half];
                mv = fmaxf(mv, __shfl_xor_sync(0xFFFFFFFFu, mv, 1));
                mv = fmaxf(mv, __shfl_xor_sync(0xFFFFFFFFu, mv, 2));
                if ((lane & 3) == 0) spm[mbase + mi*16 + r + half*8][wn] = mv;
            }
        __syncthreads();
        if (t < 128) {
            float tm = fmaxf(fmaxf(spm[t][0], spm[t][1]), fmaxf(spm[t][2], spm[t][3]));
            float om = rowm[t], nm = fmaxf(om, tm);
            float sc = __expf(om - nm);
            rowm[t] = nm; rsc[t] = sc; rowl[t] *= sc;
        }
        __syncthreads();
        float psum[4][2] = {};
        #pragma unroll
        for (int mi = 0; mi < 4; mi++)
            #pragma unroll
            for (int half = 0; half < 2; half++) {
                const int row = mbase + mi*16 + r + half*8;
                const float rm = rowm[row];
                #pragma unroll
                for (int ni = 0; ni < 4; ni++) {
                    float e0 = __expf(accs[mi][ni][half*2+0] - rm);
                    float e1 = __expf(accs[mi][ni][half*2+1] - rm);
                    psum[mi][half] += e0 + e1;
                    int o = row*FA_SPP + nbs + ni*8 + c2;
                    __nv_bfloat16 hh, ll;
                    split_hl(e0,hh,ll); Ph[o+0]=hh; Pl[o+0]=ll;
                    split_hl(e1,hh,ll); Ph[o+1]=hh; Pl[o+1]=ll;
                }
            }
        #pragma unroll
        for (int mi = 0; mi < 4; mi++)
            #pragma unroll
            for (int half = 0; half < 2; half++) {
                float s = psum[mi][half];
                s += __shfl_xor_sync(0xFFFFFFFFu, s, 1);
                s += __shfl_xor_sync(0xFFFFFFFFu, s, 2);
                if ((lane & 3) == 0) ssum[mbase + mi*16 + r + half*8][wn] = s;
            }
        #pragma unroll
        for (int mi = 0; mi < 4; mi++) {
            float s0 = rsc[mbase + mi*16 + r], s1 = rsc[mbase + mi*16 + r + 8];
            #pragma unroll
            for (int ni = 0; ni < 2; ni++) {
                acco[mi][ni][0] *= s0; acco[mi][ni][1] *= s0;
                acco[mi][ni][2] *= s1; acco[mi][ni][3] *= s1;
            }
        }
        #pragma unroll
        for (int i = 0; i < 8; i++) {
            int fi = t + i*256, krow = fi >> 4, col = (fi & 15)*4;
            float4 v = *(const float4*)(Vp + (size_t)(b*SS + k0 + krow)*vld + h*DHH + col);
            __nv_bfloat16 hh, ll;
            split_hl(v.x,hh,ll); Vh[(col+0)*FA_SPP + krow]=hh; Vl[(col+0)*FA_SPP + krow]=ll;
            split_hl(v.y,hh,ll); Vh[(col+1)*FA_SPP + krow]=hh; Vl[(col+1)*FA_SPP + krow]=ll;
            split_hl(v.z,hh,ll); Vh[(col+2)*FA_SPP + krow]=hh; Vl[(col+2)*FA_SPP + krow]=ll;
            split_hl(v.w,hh,ll); Vh[(col+3)*FA_SPP + krow]=hh; Vl[(col+3)*FA_SPP + krow]=ll;
        }
        __syncthreads();
        if (t < 128) rowl[t] += ssum[t][0] + ssum[t][1] + ssum[t][2] + ssum[t][3];
        #pragma unroll
        for (int seg = 0; seg < 3; seg++) {
            const u32 ab = smem_u32((seg == 2) ? Pl : Ph);
            const u32 wb = smem_u32((seg == 1) ? Vl : Vh);
            #pragma unroll
            for (int ks = 0; ks < 8; ks++) {
                u32 af[4][4], bfr[4];
                #pragma unroll
                for (int mi = 0; mi < 4; mi++) {
                    u32 ad = ab + (u32)(((mbase + mi*16 + a_row)*FA_SPP + ks*16 + a_col)*2);
                    ldsm4(af[mi][0], af[mi][1], af[mi][2], af[mi][3], ad);
                }
                u32 bd = wb + (u32)(((nbo + b_row)*FA_SPP + ks*16 + b_col)*2);
                ldsm4(bfr[0], bfr[1], bfr[2], bfr[3], bd);
                #pragma unroll
                for (int mi = 0; mi < 4; mi++)
                    #pragma unroll
                    for (int ni = 0; ni < 2; ni++)
                        mma16816(acco[mi][ni], af[mi], &bfr[ni*2]);
            }
        }
    }
    __syncthreads();
    #pragma unroll
    for (int mi = 0; mi < 4; mi++)
        #pragma unroll
        for (int ni = 0; ni < 2; ni++)
            #pragma unroll
            for (int half = 0; half < 2; half++) {
                const int row = mbase + mi*16 + r + half*8;
                const float inv = 1.0f/rowl[row];
                float v0 = acco[mi][ni][half*2+0]*inv;
                float v1 = acco[mi][ni][half*2+1]*inv;
                size_t idx = (size_t)(b*SS + q0 + row)*DD + h*DHH + nbo + ni*8 + c2;
                __nv_bfloat16 hh, ll;
                split_hl(v0,hh,ll); oh[idx]=hh;   ol[idx]=ll;
                split_hl(v1,hh,ll); oh[idx+1]=hh; ol[idx+1]=ll;
            }
}

// ---------------- embedding ----------------
__global__ void embed_kernel(const int* __restrict__ tokens, const float* __restrict__ emb,
                             float* __restrict__ x, __nv_bfloat16* __restrict__ xh,
                             __nv_bfloat16* __restrict__ xl, float* __restrict__ depad)
{
    int row = blockIdx.x, s = row & (SS-1), tok = tokens[row];
    if (threadIdx.x == 0) depad[row] = (tok == 0) ? 1.0f : 0.0f;
    const float sq = sqrtf((float)DD);
    for (int d = threadIdx.x; d < DD; d += blockDim.x) {
        float i = (float)((d >> 1) << 1)/(float)DD;
        float em = (float)s*powf(10000.0f, -i);
        float pe = ((d & 1) == 0) ? sinf(em) : cosf(em);
        float v = emb[(size_t)tok*DD + d]*sq + pe;
        x[(size_t)row*DD + d] = v;
        __nv_bfloat16 h, l; split_hl(v, h, l);
        xh[(size_t)row*DD + d] = h; xl[(size_t)row*DD + d] = l;
    }
}

// ---------------- LayerNorm over pre-summed input (+hi/lo) -----------------
__global__ void __launch_bounds__(256)
lnorm(const float* __restrict__ xs,
      const float* __restrict__ g, const float* __restrict__ bb,
      float* __restrict__ y, __nv_bfloat16* __restrict__ yh, __nv_bfloat16* __restrict__ yl)
{
    __shared__ float red[256];
    const int row = blockIdx.x, t = threadIdx.x;
    const size_t base = (size_t)row*DD;
    float a = xs[base+t];
    float c = xs[base+t+256];
    red[t] = a + c; __syncthreads();
    for (int o = 128; o > 0; o >>= 1) { if (t < o) red[t] += red[t+o]; __syncthreads(); }
    float mu = red[0]*(1.0f/DD); __syncthreads();
    float da = a - mu, dc = c - mu;
    red[t] = da*da + dc*dc; __syncthreads();
    for (int o = 128; o > 0; o >>= 1) { if (t < o) red[t] += red[t+o]; __syncthreads(); }
    float inv = rsqrtf(red[0]*(1.0f/DD) + 1e-6f);
    float v0 = da*inv*g[t] + bb[t], v1 = dc*inv*g[t+256] + bb[t+256];
    y[base+t] = v0; y[base+t+256] = v1;
    __nv_bfloat16 hh, ll;
    split_hl(v0, hh, ll); yh[base+t] = hh;     yl[base+t] = ll;
    split_hl(v1, hh, ll); yh[base+t+256] = hh; yl[base+t+256] = ll;
}

// ---------------- launch ----------------
extern "C" void kernel_launch(void* const* d_in, const int* in_sizes, int n_in,
                              void* d_out, int out_size)
{
    const int*   tokens = (const int*)d_in[0];
    const float* en_out = (const float*)d_in[1];
    const float* en_pad = (const float*)d_in[2];
    const float* emb    = (const float*)d_in[3];
    const float* sa_w = (const float*)d_in[4],  *sa_b = (const float*)d_in[5];
    const float* ca_w = (const float*)d_in[6],  *ca_b = (const float*)d_in[7];
    const float* ff_w1 = (const float*)d_in[8], *ff_b1 = (const float*)d_in[9];
    const float* ff_w2 = (const float*)d_in[10],*ff_b2 = (const float*)d_in[11];
    const float* ln_g = (const float*)d_in[12], *ln_b = (const float*)d_in[13];
    const float* out_w = (const float*)d_in[14],*out_b = (const float*)d_in[15];
    float* out = (float*)d_out;

    float *x,*h,*a,*qkv,*ckv,*pr,*dp;
    cudaGetSymbolAddress((void**)&x,g_x); cudaGetSymbolAddress((void**)&h,g_h);
    cudaGetSymbolAddress((void**)&a,g_a); cudaGetSymbolAddress((void**)&qkv,g_qkv);
    cudaGetSymbolAddress((void**)&ckv,g_ckv);
    cudaGetSymbolAddress((void**)&pr,g_pr); cudaGetSymbolAddress((void**)&dp,g_dp);
    __nv_bfloat16 *wsah,*wsal,*wcah,*wcal,*wf1h,*wf1l,*wf2h,*wf2l,*woh,*wol,*enh,*enl;
    __nv_bfloat16 *xh,*xl,*hh,*hl,*ah,*al,*aoh,*aol,*ffh,*ffl;
    cudaGetSymbolAddress((void**)&wsah,g_wsa_h); cudaGetSymbolAddress((void**)&wsal,g_wsa_l);
    cudaGetSymbolAddress((void**)&wcah,g_wca_h); cudaGetSymbolAddress((void**)&wcal,g_wca_l);
    cudaGetSymbolAddress((void**)&wf1h,g_wf1_h); cudaGetSymbolAddress((void**)&wf1l,g_wf1_l);
    cudaGetSymbolAddress((void**)&wf2h,g_wf2_h); cudaGetSymbolAddress((void**)&wf2l,g_wf2_l);
    cudaGetSymbolAddress((void**)&woh,g_wo_h);   cudaGetSymbolAddress((void**)&wol,g_wo_l);
    cudaGetSymbolAddress((void**)&enh,g_en_h);   cudaGetSymbolAddress((void**)&enl,g_en_l);
    cudaGetSymbolAddress((void**)&xh,g_xh);   cudaGetSymbolAddress((void**)&xl,g_xl);
    cudaGetSymbolAddress((void**)&hh,g_hh);   cudaGetSymbolAddress((void**)&hl,g_hl2);
    cudaGetSymbolAddress((void**)&ah,g_ah);   cudaGetSymbolAddress((void**)&al,g_al);
    cudaGetSymbolAddress((void**)&aoh,g_aoh); cudaGetSymbolAddress((void**)&aol,g_aol);
    cudaGetSymbolAddress((void**)&ffh,g_ffh); cudaGetSymbolAddress((void**)&ffl,g_ffl);

    cudaFuncSetAttribute(tgemm<0,0,128,0>, cudaFuncAttributeMaxDynamicSharedMemorySize, DSM(128));
    cudaFuncSetAttribute(tgemm<0,0,64,1>,  cudaFuncAttributeMaxDynamicSharedMemorySize, DSM(64));
    cudaFuncSetAttribute(tgemm<0,0,64,0>,  cudaFuncAttributeMaxDynamicSharedMemorySize, DSM(64));
    cudaFuncSetAttribute(tgemm<1,1,128,0>, cudaFuncAttributeMaxDynamicSharedMemorySize, DSM(128));
    cudaFuncSetAttribute(attn_fused<0>, cudaFuncAttributeMaxDynamicSharedMemorySize, FA_DSMEM);
    cudaFuncSetAttribute(attn_fused<1>, cudaFuncAttributeMaxDynamicSharedMemorySize, FA_DSMEM);

    cvt_hl<<<NW_SA/16/256, 256>>>(sa_w, wsah, wsal, NW_SA/4);
    cvt_hl<<<NW_SA/16/256, 256>>>(ca_w, wcah, wcal, NW_SA/4);
    cvt_hl<<<NW_F1/16/256, 256>>>(ff_w1, wf1h, wf1l, NW_F1/4);
    cvt_hl<<<NW_F1/16/256, 256>>>(ff_w2, wf2h, wf2l, NW_F1/4);
    cvt_hl<<<(NW_OUT/16+255)/256, 256>>>(out_w, woh, wol, NW_OUT/4);
    cvt_hl<<<MM*DD/16/256, 256>>>(en_out, enh, enl, MM*DD/4);

    embed_kernel<<<MM, 256>>>(tokens, emb, x, xh, xl, dp);

    tgemm<0,0,128,0><<<dim3(CKVLD/128, MM/128, LL), 256, DSM(128)>>>(
        enh, enl, wcah + DD*DD, wcal + DD*DD, ca_b + DD, ckv, 0, 0, 0, DD, CKVLD,
        (size_t)4*DD*DD, (size_t)4*DD, (size_t)MM*CKVLD);

    const dim3 gF(1, SS/128, BB*HH);
    for (int i = 0; i < LL; i++) {
        const size_t w4 = (size_t)i*4*DD*DD, b4 = (size_t)i*4*DD;
        const float* kcb = ckv + (size_t)i*MM*CKVLD;
        // self attention
        tgemm<0,0,128,0><<<dim3(QKVLD/128, MM/128), 256, DSM(128)>>>(
            xh, xl, wsah+w4, wsal+w4, sa_b+b4, qkv, 0, 0, 0, DD, QKVLD, 0, 0, 0);
        attn_fused<1><<<gF, 256, FA_DSMEM>>>(qkv, QKVLD, qkv+DD, QKVLD, qkv+2*DD, QKVLD, dp, aoh, aol);
        tgemm<0,0,64,1><<<dim3(DD/128, MM/64), 256, DSM(64)>>>(
            aoh, aol, wsah+w4+3*DD*DD, wsal+w4+3*DD*DD, sa_b+b4+3*DD, pr, 0, 0, x, DD, DD, 0, 0, 0);
        lnorm<<<MM, 256>>>(pr, ln_g+(size_t)(i*3+0)*DD, ln_b+(size_t)(i*3+0)*DD, h, hh, hl);
        // cross attention (K/V precomputed)
        tgemm<0,0,64,0><<<dim3(DD/128, MM/64), 256, DSM(64)>>>(
            hh, hl, wcah+w4, wcal+w4, ca_b+b4, qkv, 0, 0, 0, DD, QKVLD, 0, 0, 0);
        attn_fused<0><<<gF, 256, FA_DSMEM>>>(qkv, QKVLD, kcb, CKVLD, kcb+DD, CKVLD, en_pad, aoh, aol);
        tgemm<0,0,64,1><<<dim3(DD/128, MM/64), 256, DSM(64)>>>(
            aoh, aol, wcah+w4+3*DD*DD, wcal+w4+3*DD*DD, ca_b+b4+3*DD, pr, 0, 0, h, DD, DD, 0, 0, 0);
        lnorm<<<MM, 256>>>(pr, ln_g+(size_t)(i*3+1)*DD, ln_b+(size_t)(i*3+1)*DD, a, ah, al);
        // feed forward
        tgemm<1,1,128,0><<<dim3(FFD/128, MM/128), 256, DSM(128)>>>(
            ah, al, wf1h+(size_t)i*FFD*DD, wf1l+(size_t)i*FFD*DD, ff_b1+(size_t)i*FFD,
            0, ffh, ffl, 0, DD, FFD, 0, 0, 0);
        tgemm<0,0,64,1><<<dim3(DD/128, MM/64), 256, DSM(64)>>>(
            ffh, ffl, wf2h+(size_t)i*FFD*DD, wf2l+(size_t)i*FFD*DD, ff_b2+(size_t)i*DD,
            pr, 0, 0, a, FFD, DD, 0, 0, 0);
        lnorm<<<MM, 256>>>(pr, ln_g+(size_t)(i*3+2)*DD, ln_b+(size_t)(i*3+2)*DD, x, xh, xl);
    }
    tgemm<0,0,128,0><<<dim3(VV/128, MM/128), 256, DSM(128)>>>(
        xh, xl, woh, wol, out_b, out, 0, 0, 0, DD, VV, 0, 0, 0);
}

// round 17
// speedup vs baseline: 1.1213x; 1.1213x over previous
#include <cuda_runtime.h>
#include <cuda_bf16.h>
#include <math.h>
#include <stdint.h>

typedef unsigned int u32; typedef unsigned long long u64;
#define BB 4
#define SS 512
#define DD 512
#define HH 8
#define DHH 64
#define FFD 2048
#define LL 6
#define VV 32000
#define MM (BB*SS)
#define QKVLD (3*DD)
#define CKVLD (2*DD)

__device__ float g_x[MM*DD], g_h[MM*DD], g_a[MM*DD], g_qkv[MM*3*DD];
__device__ float g_ckv[LL*MM*CKVLD];
__device__ float g_pr[MM*DD], g_dp[MM];
#define NW_SA (LL*4*DD*DD)
#define NW_F1 (LL*FFD*DD)
#define NW_OUT (VV*DD)
__device__ __nv_bfloat16 g_wsa_h[NW_SA], g_wsa_l[NW_SA], g_wca_h[NW_SA], g_wca_l[NW_SA];
__device__ __nv_bfloat16 g_wf1_h[NW_F1], g_wf1_l[NW_F1], g_wf2_h[NW_F1], g_wf2_l[NW_F1];
__device__ __nv_bfloat16 g_wo_h[NW_OUT], g_wo_l[NW_OUT], g_en_h[MM*DD], g_en_l[MM*DD];
__device__ __nv_bfloat16 g_xh[MM*DD], g_xl[MM*DD], g_hh[MM*DD], g_hl2[MM*DD];
__device__ __nv_bfloat16 g_ah[MM*DD], g_al[MM*DD], g_aoh[MM*DD], g_aol[MM*DD];
__device__ __nv_bfloat16 g_ffh[MM*FFD], g_ffl[MM*FFD];

__device__ __forceinline__ u32 smem_u32(const void* p) {
    u32 a; asm("{ .reg .u64 t; cvta.to.shared.u64 t, %1; cvt.u32.u64 %0, t; }" : "=r"(a) : "l"(p)); return a;
}
__device__ __forceinline__ void ldsm4(u32& r0, u32& r1, u32& r2, u32& r3, u32 addr) {
    asm volatile("ldmatrix.sync.aligned.m8n8.x4.shared.b16 {%0,%1,%2,%3}, [%4];"
                 : "=r"(r0), "=r"(r1), "=r"(r2), "=r"(r3) : "r"(addr));
}
__device__ __forceinline__ void mma16816(float* d, const u32* a, const u32* b) {
    asm volatile("mma.sync.aligned.m16n8k16.row.col.f32.bf16.bf16.f32 "
                 "{%0,%1,%2,%3}, {%4,%5,%6,%7}, {%8,%9}, {%0,%1,%2,%3};"
                 : "+f"(d[0]), "+f"(d[1]), "+f"(d[2]), "+f"(d[3])
                 : "r"(a[0]), "r"(a[1]), "r"(a[2]), "r"(a[3]), "r"(b[0]), "r"(b[1]));
}
__device__ __forceinline__ void cpa16(u32 saddr, const void* gaddr) {
    asm volatile("cp.async.cg.shared.global [%0], [%1], 16;" :: "r"(saddr), "l"(gaddr));
}
__device__ __forceinline__ void cpa_commit() { asm volatile("cp.async.commit_group;"); }
__device__ __forceinline__ void cpa_wait1()  { asm volatile("cp.async.wait_group 1;"); }
__device__ __forceinline__ void split_hl(float v, __nv_bfloat16& h, __nv_bfloat16& l) {
    h = __float2bfloat16(v); l = __float2bfloat16(v - __bfloat162float(h));
}

__global__ void cvt_hl(const float* __restrict__ s, __nv_bfloat16* __restrict__ hi,
                       __nv_bfloat16* __restrict__ lo, int n4) {
    int i = blockIdx.x*blockDim.x + threadIdx.x;
    if (i >= n4) return;
    float4 v = ((const float4*)s)[i];
    __nv_bfloat16 h, l;
    split_hl(v.x,h,l); hi[i*4+0]=h; lo[i*4+0]=l;
    split_hl(v.y,h,l); hi[i*4+1]=h; lo[i*4+1]=l;
    split_hl(v.z,h,l); hi[i*4+2]=h; lo[i*4+2]=l;
    split_hl(v.w,h,l); hi[i*4+3]=h; lo[i*4+3]=l;
}

// ==== HMMA split-3 GEMM, resident hi/lo tiles per stage, 3-stage cp.async ===
#define BK 64
#define SPITCH 72
#define TG_STAGES 3
#define WTILEE (128*SPITCH)
template<int RELU, int OUTHL, int MT, int RESID>
__global__ void __launch_bounds__(256)
tgemm(const __nv_bfloat16* __restrict__ Ah, const __nv_bfloat16* __restrict__ Al,
      const __nv_bfloat16* __restrict__ Wh, const __nv_bfloat16* __restrict__ Wl,
      const float* __restrict__ bias, float* __restrict__ C,
      __nv_bfloat16* __restrict__ Ch, __nv_bfloat16* __restrict__ Cl,
      const float* __restrict__ Res, int K, int ldc,
      size_t wstep, size_t bstep, size_t cstep)
{
    constexpr int ATILEE = MT*SPITCH;
    constexpr int STAGEE = 2*ATILEE + 2*WTILEE;
    constexpr int WM = MT/32;
    extern __shared__ __align__(16) __nv_bfloat16 sm[];
    const int zb = blockIdx.z;
    Wh += (size_t)zb*wstep; Wl += (size_t)zb*wstep;
    bias += (size_t)zb*bstep;
    if (!OUTHL) C += (size_t)zb*cstep;
    const int t = threadIdx.x, lane = t & 31, wid = t >> 5;
    const int m0 = blockIdx.y*MT, n0 = blockIdx.x*128;
    const int wm = wid >> 2, wn = wid & 3;
    const int mbase = wm*(MT/2), nbase = wn*32;
    const int mat = lane >> 3, rowin = lane & 7;
    const int a_row = (mat & 1)*8 + rowin, a_col = (mat >> 1)*8;
    const int b_row = (mat >> 1)*8 + rowin, b_col = (mat & 1)*8;
    const int wlrow = t >> 1, wlcol = (t & 1)*32;
    const int alrow = (MT == 128) ? (t >> 1) : (t >> 2);
    const int alcol = (MT == 128) ? ((t & 1)*32) : ((t & 3)*16);
    const int kc = K/BK;
    const u32 sbase = smem_u32(&sm[0]);

    float acc[WM][4][4];
    #pragma unroll
    for (int i = 0; i < WM; i++)
        #pragma unroll
        for (int j = 0; j < 4; j++)
            #pragma unroll
            for (int q = 0; q < 4; q++) acc[i][j][q] = 0.f;

    auto issue = [&](int c) {
        const int s = c % TG_STAGES;
        const int kq = c*BK;
        const __nv_bfloat16* ah = Ah + (size_t)(m0+alrow)*K + kq + alcol;
        const __nv_bfloat16* al = Al + (size_t)(m0+alrow)*K + kq + alcol;
        const __nv_bfloat16* wh = Wh + (size_t)(n0+wlrow)*K + kq + wlcol;
        const __nv_bfloat16* wl = Wl + (size_t)(n0+wlrow)*K + kq + wlcol;
        const u32 dah = sbase + (u32)((s*STAGEE + alrow*SPITCH + alcol)*2);
        const u32 dal = dah + (u32)(ATILEE*2);
        const u32 dwh = sbase + (u32)((s*STAGEE + 2*ATILEE + wlrow*SPITCH + wlcol)*2);
        const u32 dwl = dwh + (u32)(WTILEE*2);
        if (MT == 128) {
            cpa16(dah, ah); cpa16(dah+16, ah+8); cpa16(dah+32, ah+16); cpa16(dah+48, ah+24);
            cpa16(dal, al); cpa16(dal+16, al+8); cpa16(dal+32, al+16); cpa16(dal+48, al+24);
        } else {
            cpa16(dah, ah); cpa16(dah+16, ah+8);
            cpa16(dal, al); cpa16(dal+16, al+8);
        }
        cpa16(dwh, wh); cpa16(dwh+16, wh+8); cpa16(dwh+32, wh+16); cpa16(dwh+48, wh+24);
        cpa16(dwl, wl); cpa16(dwl+16, wl+8); cpa16(dwl+32, wl+16); cpa16(dwl+48, wl+24);
    };

    #pragma unroll
    for (int c = 0; c < TG_STAGES-1; c++) { issue(c); cpa_commit(); }

    for (int c = 0; c < kc; ++c) {
        cpa_wait1();
        __syncthreads();
        const int s = c % TG_STAGES;
        const u32 ahb = sbase + (u32)(s*STAGEE*2);
        const u32 alb = ahb + (u32)(ATILEE*2);
        const u32 whb = ahb + (u32)(2*ATILEE*2);
        const u32 wlb = whb + (u32)(WTILEE*2);
        #pragma unroll
        for (int seg = 0; seg < 3; seg++) {
            const u32 ab = (seg == 2) ? alb : ahb;
            const u32 wb = (seg == 1) ? wlb : whb;
            #pragma unroll
            for (int ks = 0; ks < BK/16; ks++) {
                u32 af[WM][4], bfr[2][4];
                #pragma unroll
                for (int mi = 0; mi < WM; mi++) {
                    u32 ad = ab + (u32)(((mbase + mi*16 + a_row)*SPITCH + ks*16 + a_col)*2);
                    ldsm4(af[mi][0], af[mi][1], af[mi][2], af[mi][3], ad);
                }
                #pragma unroll
                for (int g = 0; g < 2; g++) {
                    u32 bd = wb + (u32)(((nbase + g*16 + b_row)*SPITCH + ks*16 + b_col)*2);
                    ldsm4(bfr[g][0], bfr[g][1], bfr[g][2], bfr[g][3], bd);
                }
                #pragma unroll
                for (int mi = 0; mi < WM; mi++)
                    #pragma unroll
                    for (int ni = 0; ni < 4; ni++)
                        mma16816(acc[mi][ni], af[mi], &bfr[ni >> 1][(ni & 1)*2]);
            }
        }
        const int cn = c + TG_STAGES - 1;
        if (cn < kc) issue(cn);
        cpa_commit();
    }

    const int r = lane >> 2, c2 = (lane & 3) << 1;
    #pragma unroll
    for (int mi = 0; mi < WM; mi++) {
        #pragma unroll
        for (int ni = 0; ni < 4; ni++) {
            const int m = m0 + mbase + mi*16 + r;
            const int n = n0 + nbase + ni*8 + c2;
            float b0 = bias[n], b1 = bias[n+1];
            float v0 = acc[mi][ni][0] + b0, v1 = acc[mi][ni][1] + b1;
            float v2 = acc[mi][ni][2] + b0, v3 = acc[mi][ni][3] + b1;
            if (RESID) {
                float2 r0 = *(const float2*)(Res + (size_t)m*ldc + n);
                float2 r1 = *(const float2*)(Res + (size_t)(m+8)*ldc + n);
                v0 += r0.x; v1 += r0.y; v2 += r1.x; v3 += r1.y;
            }
            if (RELU) { v0=fmaxf(v0,0.f); v1=fmaxf(v1,0.f); v2=fmaxf(v2,0.f); v3=fmaxf(v3,0.f); }
            if (OUTHL) {
                __nv_bfloat16 h, l;
                size_t i0 = (size_t)m*ldc + n, i1 = (size_t)(m+8)*ldc + n;
                split_hl(v0,h,l); Ch[i0]=h;   Cl[i0]=l;
                split_hl(v1,h,l); Ch[i0+1]=h; Cl[i0+1]=l;
                split_hl(v2,h,l); Ch[i1]=h;   Cl[i1]=l;
                split_hl(v3,h,l); Ch[i1+1]=h; Cl[i1+1]=l;
            } else {
                *(float2*)(C + (size_t)m*ldc + n)     = make_float2(v0, v1);
                *(float2*)(C + (size_t)(m+8)*ldc + n) = make_float2(v2, v3);
            }
        }
    }
}
#define DSM(MT) (TG_STAGES*2*((MT)+128)*SPITCH*2)

// ======== fused flash attention =============================================
#define FA_SPQ 72
#define FA_SPP 136
#define FA_QE (128*FA_SPQ)
#define FA_PE (128*FA_SPP)
#define FA_VE (64*FA_SPP)
#define FA_DSMEM ((4*FA_QE + 2*FA_PE + 2*FA_VE)*2)
template<int CAUSAL>
__global__ void __launch_bounds__(256)
attn_fused(const float* __restrict__ Qp, int qld,
           const float* __restrict__ Kp, int kld,
           const float* __restrict__ Vp, int vld,
           const float* __restrict__ mask,
           __nv_bfloat16* __restrict__ oh, __nv_bfloat16* __restrict__ ol)
{
    extern __shared__ __align__(16) __nv_bfloat16 sm[];
    __nv_bfloat16 *Qh = sm,          *Ql = Qh + FA_QE;
    __nv_bfloat16 *Kh = Ql + FA_QE,  *Kl = Kh + FA_QE;
    __nv_bfloat16 *Ph = Kl + FA_QE,  *Pl = Ph + FA_PE;
    __nv_bfloat16 *Vh = Pl + FA_PE,  *Vl = Vh + FA_VE;
    __shared__ float rowm[128], rowl[128], rsc[128];
    __shared__ float spm[128][4], ssum[128][4];
    const int z = blockIdx.z, b = z >> 3, h = z & 7;
    const int q0 = blockIdx.y*128;
    const int t = threadIdx.x, lane = t & 31, wid = t >> 5;
    const int wm = wid >> 2, wn = wid & 3;
    const int mbase = wm*64, nbs = wn*32, nbo = wn*16;
    const int mat = lane >> 3, rowin = lane & 7;
    const int a_row = (mat & 1)*8 + rowin, a_col = (mat >> 1)*8;
    const int b_row = (mat >> 1)*8 + rowin, b_col = (mat & 1)*8;
    const int r = lane >> 2, c2 = (lane & 3) << 1;

    #pragma unroll
    for (int i = 0; i < 8; i++) {
        int fi = t + i*256, row = fi >> 4, col = (fi & 15)*4;
        float4 qv = *(const float4*)(Qp + (size_t)(b*SS + q0 + row)*qld + h*DHH + col);
        __nv_bfloat16 hh, ll; int o = row*FA_SPQ + col;
        split_hl(qv.x,hh,ll); Qh[o+0]=hh; Ql[o+0]=ll;
        split_hl(qv.y,hh,ll); Qh[o+1]=hh; Ql[o+1]=ll;
        split_hl(qv.z,hh,ll); Qh[o+2]=hh; Ql[o+2]=ll;
        split_hl(qv.w,hh,ll); Qh[o+3]=hh; Ql[o+3]=ll;
    }
    if (t < 128) { rowm[t] = -1e30f; rowl[t] = 0.f; }
    float acco[4][2][4];
    #pragma unroll
    for (int i = 0; i < 4; i++)
        #pragma unroll
        for (int j = 0; j < 2; j++)
            #pragma unroll
            for (int q = 0; q < 4; q++) acco[i][j][q] = 0.f;
    __syncthreads();

    for (int kt = 0; kt < 4; kt++) {
        const int k0 = kt*128;
        #pragma unroll
        for (int i = 0; i < 8; i++) {
            int fi = t + i*256, row = fi >> 4, col = (fi & 15)*4;
            float4 kv = *(const float4*)(Kp + (size_t)(b*SS + k0 + row)*kld + h*DHH + col);
            __nv_bfloat16 hh, ll; int o = row*FA_SPQ + col;
            split_hl(kv.x,hh,ll); Kh[o+0]=hh; Kl[o+0]=ll;
            split_hl(kv.y,hh,ll); Kh[o+1]=hh; Kl[o+1]=ll;
            split_hl(kv.z,hh,ll); Kh[o+2]=hh; Kl[o+2]=ll;
            split_hl(kv.w,hh,ll); Kh[o+3]=hh; Kl[o+3]=ll;
        }
        __syncthreads();
        float accs[4][4][4];
        #pragma unroll
        for (int i = 0; i < 4; i++)
            #pragma unroll
            for (int j = 0; j < 4; j++)
                #pragma unroll
                for (int q = 0; q < 4; q++) accs[i][j][q] = 0.f;
        #pragma unroll
        for (int seg = 0; seg < 3; seg++) {
            const u32 ab = smem_u32((seg == 2) ? Ql : Qh);
            const u32 wb = smem_u32((seg == 1) ? Kl : Kh);
            #pragma unroll
            for (int ks = 0; ks < 4; ks++) {
                u32 af[4][4], bfr[2][4];
                #pragma unroll
                for (int mi = 0; mi < 4; mi++) {
                    u32 ad = ab + (u32)(((mbase + mi*16 + a_row)*FA_SPQ + ks*16 + a_col)*2);
                    ldsm4(af[mi][0], af[mi][1], af[mi][2], af[mi][3], ad);
                }
                #pragma unroll
                for (int g = 0; g < 2; g++) {
                    u32 bd = wb + (u32)(((nbs + g*16 + b_row)*FA_SPQ + ks*16 + b_col)*2);
                    ldsm4(bfr[g][0], bfr[g][1], bfr[g][2], bfr[g][3], bd);
                }
                #pragma unroll
                for (int mi = 0; mi < 4; mi++)
                    #pragma unroll
                    for (int ni = 0; ni < 4; ni++)
                        mma16816(accs[mi][ni], af[mi], &bfr[ni >> 1][(ni & 1)*2]);
            }
        }
        float rmax[4][2];
        #pragma unroll
        for (int mi = 0; mi < 4; mi++) { rmax[mi][0] = -1e30f; rmax[mi][1] = -1e30f; }
        #pragma unroll
        for (int mi = 0; mi < 4; mi++)
            #pragma unroll
            for (int ni = 0; ni < 4; ni++)
                #pragma unroll
                for (int half = 0; half < 2; half++) {
                    const int m = q0 + mbase + mi*16 + r + half*8;
                    const int n = k0 + nbs + ni*8 + c2;
                    float mv0 = mask[b*SS + n], mv1 = mask[b*SS + n + 1];
                    if (CAUSAL && n   > m) mv0 = 1.0f;
                    if (CAUSAL && n+1 > m) mv1 = 1.0f;
                    float v0 = accs[mi][ni][half*2+0]*0.125f - mv0*1e6f;
                    float v1 = accs[mi][ni][half*2+1]*0.125f - mv1*1e6f;
                    accs[mi][ni][half*2+0] = v0; accs[mi][ni][half*2+1] = v1;
                    rmax[mi][half] = fmaxf(rmax[mi][half], fmaxf(v0, v1));
                }
        #pragma unroll
        for (int mi = 0; mi < 4; mi++)
            #pragma unroll
            for (int half = 0; half < 2; half++) {
                float mv = rmax[mi][half];
                mv = fmaxf(mv, __shfl_xor_sync(0xFFFFFFFFu, mv, 1));
                mv = fmaxf(mv, __shfl_xor_sync(0xFFFFFFFFu, mv, 2));
                if ((lane & 3) == 0) spm[mbase + mi*16 + r + half*8][wn] = mv;
            }
        __syncthreads();
        if (t < 128) {
            float tm = fmaxf(fmaxf(spm[t][0], spm[t][1]), fmaxf(spm[t][2], spm[t][3]));
            float om = rowm[t], nm = fmaxf(om, tm);
            float sc = __expf(om - nm);
            rowm[t] = nm; rsc[t] = sc; rowl[t] *= sc;
        }
        __syncthreads();
        float psum[4][2] = {};
        #pragma unroll
        for (int mi = 0; mi < 4; mi++)
            #pragma unroll
            for (int half = 0; half < 2; half++) {
                const int row = mbase + mi*16 + r + half*8;
                const float rm = rowm[row];
                #pragma unroll
                for (int ni = 0; ni < 4; ni++) {
                    float e0 = __expf(accs[mi][ni][half*2+0] - rm);
                    float e1 = __expf(accs[mi][ni][half*2+1] - rm);
                    psum[mi][half] += e0 + e1;
                    int o = row*FA_SPP + nbs + ni*8 + c2;
                    __nv_bfloat16 hh, ll;
                    split_hl(e0,hh,ll); Ph[o+0]=hh; Pl[o+0]=ll;
                    split_hl(e1,hh,ll); Ph[o+1]=hh; Pl[o+1]=ll;
                }
            }
        #pragma unroll
        for (int mi = 0; mi < 4; mi++)
            #pragma unroll
            for (int half = 0; half < 2; half++) {
                float s = psum[mi][half];
                s += __shfl_xor_sync(0xFFFFFFFFu, s, 1);
                s += __shfl_xor_sync(0xFFFFFFFFu, s, 2);
                if ((lane & 3) == 0) ssum[mbase + mi*16 + r + half*8][wn] = s;
            }
        #pragma unroll
        for (int mi = 0; mi < 4; mi++) {
            float s0 = rsc[mbase + mi*16 + r], s1 = rsc[mbase + mi*16 + r + 8];
            #pragma unroll
            for (int ni = 0; ni < 2; ni++) {
                acco[mi][ni][0] *= s0; acco[mi][ni][1] *= s0;
                acco[mi][ni][2] *= s1; acco[mi][ni][3] *= s1;
            }
        }
        #pragma unroll
        for (int i = 0; i < 8; i++) {
            int fi = t + i*256, krow = fi >> 4, col = (fi & 15)*4;
            float4 v = *(const float4*)(Vp + (size_t)(b*SS + k0 + krow)*vld + h*DHH + col);
            __nv_bfloat16 hh, ll;
            split_hl(v.x,hh,ll); Vh[(col+0)*FA_SPP + krow]=hh; Vl[(col+0)*FA_SPP + krow]=ll;
            split_hl(v.y,hh,ll); Vh[(col+1)*FA_SPP + krow]=hh; Vl[(col+1)*FA_SPP + krow]=ll;
            split_hl(v.z,hh,ll); Vh[(col+2)*FA_SPP + krow]=hh; Vl[(col+2)*FA_SPP + krow]=ll;
            split_hl(v.w,hh,ll); Vh[(col+3)*FA_SPP + krow]=hh; Vl[(col+3)*FA_SPP + krow]=ll;
        }
        __syncthreads();
        if (t < 128) rowl[t] += ssum[t][0] + ssum[t][1] + ssum[t][2] + ssum[t][3];
        #pragma unroll
        for (int seg = 0; seg < 3; seg++) {
            const u32 ab = smem_u32((seg == 2) ? Pl : Ph);
            const u32 wb = smem_u32((seg == 1) ? Vl : Vh);
            #pragma unroll
            for (int ks = 0; ks < 8; ks++) {
                u32 af[4][4], bfr[4];
                #pragma unroll
                for (int mi = 0; mi < 4; mi++) {
                    u32 ad = ab + (u32)(((mbase + mi*16 + a_row)*FA_SPP + ks*16 + a_col)*2);
                    ldsm4(af[mi][0], af[mi][1], af[mi][2], af[mi][3], ad);
                }
                u32 bd = wb + (u32)(((nbo + b_row)*FA_SPP + ks*16 + b_col)*2);
                ldsm4(bfr[0], bfr[1], bfr[2], bfr[3], bd);
                #pragma unroll
                for (int mi = 0; mi < 4; mi++)
                    #pragma unroll
                    for (int ni = 0; ni < 2; ni++)
                        mma16816(acco[mi][ni], af[mi], &bfr[ni*2]);
            }
        }
    }
    __syncthreads();
    #pragma unroll
    for (int mi = 0; mi < 4; mi++)
        #pragma unroll
        for (int ni = 0; ni < 2; ni++)
            #pragma unroll
            for (int half = 0; half < 2; half++) {
                const int row = mbase + mi*16 + r + half*8;
                const float inv = 1.0f/rowl[row];
                float v0 = acco[mi][ni][half*2+0]*inv;
                float v1 = acco[mi][ni][half*2+1]*inv;
                size_t idx = (size_t)(b*SS + q0 + row)*DD + h*DHH + nbo + ni*8 + c2;
                __nv_bfloat16 hh, ll;
                split_hl(v0,hh,ll); oh[idx]=hh;   ol[idx]=ll;
                split_hl(v1,hh,ll); oh[idx+1]=hh; ol[idx+1]=ll;
            }
}

// ---------------- embedding ----------------
__global__ void embed_kernel(const int* __restrict__ tokens, const float* __restrict__ emb,
                             float* __restrict__ x, __nv_bfloat16* __restrict__ xh,
                             __nv_bfloat16* __restrict__ xl, float* __restrict__ depad)
{
    int row = blockIdx.x, s = row & (SS-1), tok = tokens[row];
    if (threadIdx.x == 0) depad[row] = (tok == 0) ? 1.0f : 0.0f;
    const float sq = sqrtf((float)DD);
    for (int d = threadIdx.x; d < DD; d += blockDim.x) {
        float i = (float)((d >> 1) << 1)/(float)DD;
        float em = (float)s*powf(10000.0f, -i);
        float pe = ((d & 1) == 0) ? sinf(em) : cosf(em);
        float v = emb[(size_t)tok*DD + d]*sq + pe;
        x[(size_t)row*DD + d] = v;
        __nv_bfloat16 h, l; split_hl(v, h, l);
        xh[(size_t)row*DD + d] = h; xl[(size_t)row*DD + d] = l;
    }
}

// ---------------- LayerNorm over pre-summed input (+hi/lo) -----------------
__global__ void __launch_bounds__(256)
lnorm(const float* __restrict__ xs,
      const float* __restrict__ g, const float* __restrict__ bb,
      float* __restrict__ y, __nv_bfloat16* __restrict__ yh, __nv_bfloat16* __restrict__ yl)
{
    __shared__ float red[256];
    const int row = blockIdx.x, t = threadIdx.x;
    const size_t base = (size_t)row*DD;
    float a = xs[base+t];
    float c = xs[base+t+256];
    red[t] = a + c; __syncthreads();
    for (int o = 128; o > 0; o >>= 1) { if (t < o) red[t] += red[t+o]; __syncthreads(); }
    float mu = red[0]*(1.0f/DD); __syncthreads();
    float da = a - mu, dc = c - mu;
    red[t] = da*da + dc*dc; __syncthreads();
    for (int o = 128; o > 0; o >>= 1) { if (t < o) red[t] += red[t+o]; __syncthreads(); }
    float inv = rsqrtf(red[0]*(1.0f/DD) + 1e-6f);
    float v0 = da*inv*g[t] + bb[t], v1 = dc*inv*g[t+256] + bb[t+256];
    y[base+t] = v0; y[base+t+256] = v1;
    __nv_bfloat16 hh, ll;
    split_hl(v0, hh, ll); yh[base+t] = hh;     yl[base+t] = ll;
    split_hl(v1, hh, ll); yh[base+t+256] = hh; yl[base+t+256] = ll;
}

// ---------------- launch ----------------
extern "C" void kernel_launch(void* const* d_in, const int* in_sizes, int n_in,
                              void* d_out, int out_size)
{
    const int*   tokens = (const int*)d_in[0];
    const float* en_out = (const float*)d_in[1];
    const float* en_pad = (const float*)d_in[2];
    const float* emb    = (const float*)d_in[3];
    const float* sa_w = (const float*)d_in[4],  *sa_b = (const float*)d_in[5];
    const float* ca_w = (const float*)d_in[6],  *ca_b = (const float*)d_in[7];
    const float* ff_w1 = (const float*)d_in[8], *ff_b1 = (const float*)d_in[9];
    const float* ff_w2 = (const float*)d_in[10],*ff_b2 = (const float*)d_in[11];
    const float* ln_g = (const float*)d_in[12], *ln_b = (const float*)d_in[13];
    const float* out_w = (const float*)d_in[14],*out_b = (const float*)d_in[15];
    float* out = (float*)d_out;

    float *x,*h,*a,*qkv,*ckv,*pr,*dp;
    cudaGetSymbolAddress((void**)&x,g_x); cudaGetSymbolAddress((void**)&h,g_h);
    cudaGetSymbolAddress((void**)&a,g_a); cudaGetSymbolAddress((void**)&qkv,g_qkv);
    cudaGetSymbolAddress((void**)&ckv,g_ckv);
    cudaGetSymbolAddress((void**)&pr,g_pr); cudaGetSymbolAddress((void**)&dp,g_dp);
    __nv_bfloat16 *wsah,*wsal,*wcah,*wcal,*wf1h,*wf1l,*wf2h,*wf2l,*woh,*wol,*enh,*enl;
    __nv_bfloat16 *xh,*xl,*hh,*hl,*ah,*al,*aoh,*aol,*ffh,*ffl;
    cudaGetSymbolAddress((void**)&wsah,g_wsa_h); cudaGetSymbolAddress((void**)&wsal,g_wsa_l);
    cudaGetSymbolAddress((void**)&wcah,g_wca_h); cudaGetSymbolAddress((void**)&wcal,g_wca_l);
    cudaGetSymbolAddress((void**)&wf1h,g_wf1_h); cudaGetSymbolAddress((void**)&wf1l,g_wf1_l);
    cudaGetSymbolAddress((void**)&wf2h,g_wf2_h); cudaGetSymbolAddress((void**)&wf2l,g_wf2_l);
    cudaGetSymbolAddress((void**)&woh,g_wo_h);   cudaGetSymbolAddress((void**)&wol,g_wo_l);
    cudaGetSymbolAddress((void**)&enh,g_en_h);   cudaGetSymbolAddress((void**)&enl,g_en_l);
    cudaGetSymbolAddress((void**)&xh,g_xh);   cudaGetSymbolAddress((void**)&xl,g_xl);
    cudaGetSymbolAddress((void**)&hh,g_hh);   cudaGetSymbolAddress((void**)&hl,g_hl2);
    cudaGetSymbolAddress((void**)&ah,g_ah);   cudaGetSymbolAddress((void**)&al,g_al);
    cudaGetSymbolAddress((void**)&aoh,g_aoh); cudaGetSymbolAddress((void**)&aol,g_aol);
    cudaGetSymbolAddress((void**)&ffh,g_ffh); cudaGetSymbolAddress((void**)&ffl,g_ffl);

    cudaFuncSetAttribute(tgemm<0,0,128,0>, cudaFuncAttributeMaxDynamicSharedMemorySize, DSM(128));
    cudaFuncSetAttribute(tgemm<0,0,64,1>,  cudaFuncAttributeMaxDynamicSharedMemorySize, DSM(64));
    cudaFuncSetAttribute(tgemm<0,0,64,0>,  cudaFuncAttributeMaxDynamicSharedMemorySize, DSM(64));
    cudaFuncSetAttribute(tgemm<1,1,128,0>, cudaFuncAttributeMaxDynamicSharedMemorySize, DSM(128));
    cudaFuncSetAttribute(attn_fused<0>, cudaFuncAttributeMaxDynamicSharedMemorySize, FA_DSMEM);
    cudaFuncSetAttribute(attn_fused<1>, cudaFuncAttributeMaxDynamicSharedMemorySize, FA_DSMEM);

    cvt_hl<<<NW_SA/4/256, 256>>>(sa_w, wsah, wsal, NW_SA/4);
    cvt_hl<<<NW_SA/4/256, 256>>>(ca_w, wcah, wcal, NW_SA/4);
    cvt_hl<<<NW_F1/4/256, 256>>>(ff_w1, wf1h, wf1l, NW_F1/4);
    cvt_hl<<<NW_F1/4/256, 256>>>(ff_w2, wf2h, wf2l, NW_F1/4);
    cvt_hl<<<NW_OUT/4/256, 256>>>(out_w, woh, wol, NW_OUT/4);
    cvt_hl<<<MM*DD/4/256, 256>>>(en_out, enh, enl, MM*DD/4);

    embed_kernel<<<MM, 256>>>(tokens, emb, x, xh, xl, dp);

    tgemm<0,0,128,0><<<dim3(CKVLD/128, MM/128, LL), 256, DSM(128)>>>(
        enh, enl, wcah + DD*DD, wcal + DD*DD, ca_b + DD, ckv, 0, 0, 0, DD, CKVLD,
        (size_t)4*DD*DD, (size_t)4*DD, (size_t)MM*CKVLD);

    const dim3 gF(1, SS/128, BB*HH);
    for (int i = 0; i < LL; i++) {
        const size_t w4 = (size_t)i*4*DD*DD, b4 = (size_t)i*4*DD;
        const float* kcb = ckv + (size_t)i*MM*CKVLD;
        // self attention
        tgemm<0,0,128,0><<<dim3(QKVLD/128, MM/128), 256, DSM(128)>>>(
            xh, xl, wsah+w4, wsal+w4, sa_b+b4, qkv, 0, 0, 0, DD, QKVLD, 0, 0, 0);
        attn_fused<1><<<gF, 256, FA_DSMEM>>>(qkv, QKVLD, qkv+DD, QKVLD, qkv+2*DD, QKVLD, dp, aoh, aol);
        tgemm<0,0,64,1><<<dim3(DD/128, MM/64), 256, DSM(64)>>>(
            aoh, aol, wsah+w4+3*DD*DD, wsal+w4+3*DD*DD, sa_b+b4+3*DD, pr, 0, 0, x, DD, DD, 0, 0, 0);
        lnorm<<<MM, 256>>>(pr, ln_g+(size_t)(i*3+0)*DD, ln_b+(size_t)(i*3+0)*DD, h, hh, hl);
        // cross attention (K/V precomputed)
        tgemm<0,0,64,0><<<dim3(DD/128, MM/64), 256, DSM(64)>>>(
            hh, hl, wcah+w4, wcal+w4, ca_b+b4, qkv, 0, 0, 0, DD, QKVLD, 0, 0, 0);
        attn_fused<0><<<gF, 256, FA_DSMEM>>>(qkv, QKVLD, kcb, CKVLD, kcb+DD, CKVLD, en_pad, aoh, aol);
        tgemm<0,0,64,1><<<dim3(DD/128, MM/64), 256, DSM(64)>>>(
            aoh, aol, wcah+w4+3*DD*DD, wcal+w4+3*DD*DD, ca_b+b4+3*DD, pr, 0, 0, h, DD, DD, 0, 0, 0);
        lnorm<<<MM, 256>>>(pr, ln_g+(size_t)(i*3+1)*DD, ln_b+(size_t)(i*3+1)*DD, a, ah, al);
        // feed forward
        tgemm<1,1,128,0><<<dim3(FFD/128, MM/128), 256, DSM(128)>>>(
            ah, al, wf1h+(size_t)i*FFD*DD, wf1l+(size_t)i*FFD*DD, ff_b1+(size_t)i*FFD,
            0, ffh, ffl, 0, DD, FFD, 0, 0, 0);
        tgemm<0,0,64,1><<<dim3(DD/128, MM/64), 256, DSM(64)>>>(
            ffh, ffl, wf2h+(size_t)i*FFD*DD, wf2l+(size_t)i*FFD*DD, ff_b2+(size_t)i*DD,
            pr, 0, 0, a, FFD, DD, 0, 0, 0);
        lnorm<<<MM, 256>>>(pr, ln_g+(size_t)(i*3+2)*DD, ln_b+(size_t)(i*3+2)*DD, x, xh, xl);
    }
    tgemm<0,0,128,0><<<dim3(VV/128, MM/128), 256, DSM(128)>>>(
        xh, xl, woh, wol, out_b, out, 0, 0, 0, DD, VV, 0, 0, 0);
}